// round 9
// baseline (speedup 1.0000x reference)
#include <cuda_runtime.h>
#include <math.h>

// Problem constants
#define Bn 2
#define Cc 512
#define Hh 64
#define Ww 64
#define Ll 4096            // H*W
#define N2 1024            // (H/2)*(W/2)
#define NHEADS 8
#define DK 64
#define Rr 63
#define ATT_SCALE (1.0f/4096.0f)   // 1/DK^2

// Scratch (static device globals — no allocation in kernel_launch).
// __align__(16): these are accessed through float4* in the GEMM kernels.
__device__ __align__(16) float g_q[Bn*Cc*Ll];        // q conv output        [B][C][L]
__device__ __align__(16) float g_im[Bn*2048*N2];     // im2col for 2x2 conv  [B][2048][n]
__device__ __align__(16) float g_t[Bn*Cc*N2];        // offset trunk         [B][C][n]
__device__ __align__(16) float g_pos[Bn*N2*2];       // sampling positions   [B][n][(y,x)]
__device__ __align__(16) float g_sm[Bn*Cc*N2];       // sampled x            [B][C][n]
__device__ __align__(16) float g_kv[Bn*2*Cc*N2];     // k|v                  [B][2C][n]
__device__ __align__(16) float g_ao[Bn*Cc*Ll];       // attention output     [B][C][L]

// ---------------------------------------------------------------------------
// Generic SGEMM: Y[M,N] = W[M,K] @ X[K,N] + bias.  64x64 tile, 4x4 microtile,
// 256 threads, k-step 16. Batched via blockIdx.z with X/Y strides.
// ---------------------------------------------------------------------------
__global__ void sgemm_bias(const float* __restrict__ W, const float* __restrict__ X,
                           const float* __restrict__ bias, float* __restrict__ Y,
                           int M, int N, int K, long sX, long sY)
{
    const float* Xb = X + (long)blockIdx.z * sX;
    float* Yb = Y + (long)blockIdx.z * sY;
    int m0 = blockIdx.y * 64, n0 = blockIdx.x * 64;
    __shared__ __align__(16) float As[16][68];   // A transposed: As[k][m]; 272B rows (16B mult)
    __shared__ __align__(16) float Bs[16][64];   // 256B rows
    int tid = threadIdx.x;
    int ai = tid >> 2, aj = (tid & 3) << 2;    // A load: row m0+ai, k offset aj
    int br = tid >> 4, bc = (tid & 15) << 2;   // B load: k row br, col bc
    int ty = tid >> 4, tx = tid & 15;
    float acc[4][4] = {};
    for (int k0 = 0; k0 < K; k0 += 16) {
        float4 av = *(const float4*)(W  + (long)(m0+ai)*K + k0 + aj);
        float4 bv = *(const float4*)(Xb + (long)(k0+br)*N + n0 + bc);
        __syncthreads();   // previous compute done before overwriting smem
        As[aj+0][ai]=av.x; As[aj+1][ai]=av.y; As[aj+2][ai]=av.z; As[aj+3][ai]=av.w;
        *(float4*)&Bs[br][bc] = bv;
        __syncthreads();
#pragma unroll
        for (int kk = 0; kk < 16; kk++) {
            float4 a  = *(float4*)&As[kk][ty<<2];
            float4 bq = *(float4*)&Bs[kk][tx<<2];
            acc[0][0]+=a.x*bq.x; acc[0][1]+=a.x*bq.y; acc[0][2]+=a.x*bq.z; acc[0][3]+=a.x*bq.w;
            acc[1][0]+=a.y*bq.x; acc[1][1]+=a.y*bq.y; acc[1][2]+=a.y*bq.z; acc[1][3]+=a.y*bq.w;
            acc[2][0]+=a.z*bq.x; acc[2][1]+=a.z*bq.y; acc[2][2]+=a.z*bq.z; acc[2][3]+=a.z*bq.w;
            acc[3][0]+=a.w*bq.x; acc[3][1]+=a.w*bq.y; acc[3][2]+=a.w*bq.z; acc[3][3]+=a.w*bq.w;
        }
    }
#pragma unroll
    for (int i = 0; i < 4; i++) {
        float bb = bias ? bias[m0+(ty<<2)+i] : 0.0f;
        float* yr = Yb + (long)(m0+(ty<<2)+i)*N + n0 + (tx<<2);
#pragma unroll
        for (int j = 0; j < 4; j++) yr[j] = acc[i][j] + bb;
    }
}

// ---------------------------------------------------------------------------
// im2col for the 2x2 stride-2 conv: im[b][ci*4+ky*2+kx][py*32+px] =
//   q[b][ci][(2py+ky)*64 + 2px+kx]   (matches off1_w [C,C,2,2] layout)
// ---------------------------------------------------------------------------
__global__ void im2col_kernel(const float* __restrict__ q, float* __restrict__ im)
{
    int idx = blockIdx.x * 256 + threadIdx.x;   // exactly B*2048*1024 threads
    int p = idx & 1023;
    int k = (idx >> 10) & 2047;
    int b = idx >> 21;
    int ci = k >> 2, ky = (k >> 1) & 1, kx = k & 1;
    int py = p >> 5, px = p & 31;
    im[idx] = q[((long)b*Cc + ci)*Ll + (2*py+ky)*Ww + 2*px + kx];
}

// ---------------------------------------------------------------------------
// GroupNorm (32 groups of 16 ch x 1024) + exact GELU, in place on g_t.
// One block per (b, group).
// ---------------------------------------------------------------------------
__global__ void gn_gelu_kernel(float* __restrict__ t, const float* __restrict__ w,
                               const float* __restrict__ b)
{
    int bb = blockIdx.x >> 5, g = blockIdx.x & 31;
    float* base = t + ((long)bb*Cc + g*16)*N2;
    int tid = threadIdx.x;
    float s = 0.0f, s2 = 0.0f;
    for (int i = tid; i < 16*N2; i += 256) { float v = base[i]; s += v; s2 += v*v; }
    __shared__ float r1[256], r2[256];
    r1[tid] = s; r2[tid] = s2;
    __syncthreads();
    for (int o = 128; o > 0; o >>= 1) {
        if (tid < o) { r1[tid] += r1[tid+o]; r2[tid] += r2[tid+o]; }
        __syncthreads();
    }
    float mu  = r1[0] * (1.0f/16384.0f);
    float var = r2[0] * (1.0f/16384.0f) - mu*mu;
    float rstd = rsqrtf(var + 1e-5f);
    for (int i = tid; i < 16*N2; i += 256) {
        int c = g*16 + (i >> 10);
        float v = (base[i] - mu) * rstd * w[c] + b[c];
        base[i] = 0.5f * v * (1.0f + erff(v * 0.70710678118654752f));
    }
}

// ---------------------------------------------------------------------------
// offset conv (off2_w [2,512], no bias) + reference grid + clip -> g_pos[b][n][(y,x)]
// One warp per position.
// ---------------------------------------------------------------------------
__global__ void offset_pos_kernel(const float* __restrict__ t, const float* __restrict__ w2,
                                  float* __restrict__ pos)
{
    int gid = blockIdx.x * 8 + (threadIdx.x >> 5);   // b*1024 + n
    int lane = threadIdx.x & 31;
    int b = gid >> 10, n = gid & 1023;
    const float* tb = t + (long)b*Cc*N2 + n;
    float sy = 0.0f, sx = 0.0f;
    for (int c = lane; c < Cc; c += 32) {
        float tv = tb[(long)c*N2];
        sy += w2[c]      * tv;   // channel 0 -> y offset
        sx += w2[Cc + c] * tv;   // channel 1 -> x offset
    }
#pragma unroll
    for (int o = 16; o > 0; o >>= 1) {
        sy += __shfl_down_sync(0xffffffffu, sy, o);
        sx += __shfl_down_sync(0xffffffffu, sx, o);
    }
    if (lane == 0) {
        int iy = n >> 5, ix = n & 31;
        float ry = (0.5f + (float)iy) / 31.0f * 2.0f - 1.0f;
        float rx = (0.5f + (float)ix) / 31.0f * 2.0f - 1.0f;
        pos[gid*2+0] = fminf(fmaxf(sy + ry, -1.0f), 1.0f);
        pos[gid*2+1] = fminf(fmaxf(sx + rx, -1.0f), 1.0f);
    }
}

// ---------------------------------------------------------------------------
// Bilinear grid_sample of x at pos -> g_sm[b][c][n].  One block per (b,n).
// ---------------------------------------------------------------------------
__global__ void sample_kernel(const float* __restrict__ x, const float* __restrict__ pos,
                              float* __restrict__ sm)
{
    int gid = blockIdx.x;
    int b = gid >> 10, n = gid & 1023;
    float py = pos[gid*2+0], px = pos[gid*2+1];
    float fx = (px + 1.0f) * 0.5f * 63.0f;
    float fy = (py + 1.0f) * 0.5f * 63.0f;
    float x0f = floorf(fx), y0f = floorf(fy);
    float wx = fx - x0f, wy = fy - y0f;
    int x0 = min(max((int)x0f, 0), 63), y0 = min(max((int)y0f, 0), 63);
    int x1 = min(x0+1, 63), y1 = min(y0+1, 63);
    float w00 = (1.0f-wx)*(1.0f-wy), w01 = wx*(1.0f-wy);
    float w10 = (1.0f-wx)*wy,        w11 = wx*wy;
    const float* xb = x + (long)b*Cc*Ll;
    for (int c = threadIdx.x; c < Cc; c += 128) {
        const float* xc = xb + (long)c*Ll;
        float v = xc[y0*64+x0]*w00 + xc[y0*64+x1]*w01
                + xc[y1*64+x0]*w10 + xc[y1*64+x1]*w11;
        sm[((long)b*Cc + c)*N2 + n] = v;
    }
}

// ---------------------------------------------------------------------------
// Fused attention: QK^T*scale + bilinear RPE bias + online softmax + PV.
// One thread per query (128 queries/block), K/V staged n-major in smem,
// head RPE table (63x63) in smem.
// ---------------------------------------------------------------------------
__global__ __launch_bounds__(128, 1)
void attn_kernel(const float* __restrict__ q, const float* __restrict__ kv,
                 const float* __restrict__ pos, const float* __restrict__ rpe,
                 float* __restrict__ out)
{
    int bh = blockIdx.y; int b = bh >> 3, h = bh & 7;
    int m = blockIdx.x * 128 + threadIdx.x;
    __shared__ __align__(16) float Ks[32][68];   // [n-in-tile][dk]; 272B rows (16B mult)
    __shared__ __align__(16) float Vs[32][68];
    __shared__ float rs[Rr*Rr];
    __shared__ float ps[64];       // pos (y,x) for the n-tile
    const float* rh = rpe + h*Rr*Rr;
    for (int i = threadIdx.x; i < Rr*Rr; i += 128) rs[i] = rh[i];

    const float* qb = q + ((long)b*Cc + h*DK)*Ll + m;
    float4 qr[16];
#pragma unroll
    for (int d4 = 0; d4 < 16; d4++) {   // pre-scale q by 1/DK^2
        qr[d4].x = qb[(d4*4+0)*Ll] * ATT_SCALE;
        qr[d4].y = qb[(d4*4+1)*Ll] * ATT_SCALE;
        qr[d4].z = qb[(d4*4+2)*Ll] * ATT_SCALE;
        qr[d4].w = qb[(d4*4+3)*Ll] * ATT_SCALE;
    }
    float qgy = (float)(m >> 6) / 63.0f * 2.0f - 1.0f;
    float qgx = (float)(m & 63) / 63.0f * 2.0f - 1.0f;

    float acc[64];
#pragma unroll
    for (int c = 0; c < 64; c++) acc[c] = 0.0f;
    float runM = -1e30f, Z = 0.0f;

    const float* kbase = kv + ((long)b*2*Cc + h*DK)*N2;
    const float* vbase = kbase + (long)Cc*N2;
    const float* pb = pos + b*N2*2;

    for (int n0 = 0; n0 < N2; n0 += 32) {
        __syncthreads();
        for (int e = threadIdx.x; e < 2048; e += 128) {
            int d = e >> 5, j = e & 31;
            Ks[j][d] = kbase[d*N2 + n0 + j];
            Vs[j][d] = vbase[d*N2 + n0 + j];
        }
        if (threadIdx.x < 64) ps[threadIdx.x] = pb[n0*2 + threadIdx.x];
        __syncthreads();

        for (int j = 0; j < 32; j++) {
            const float4* kp = (const float4*)Ks[j];
            float dot = 0.0f;
#pragma unroll
            for (int d4 = 0; d4 < 16; d4++) {
                float4 k4 = kp[d4];
                dot += qr[d4].x*k4.x; dot += qr[d4].y*k4.y;
                dot += qr[d4].z*k4.z; dot += qr[d4].w*k4.w;
            }
            // RPE bias: bilinear sample of rs at disp=((qg - pos)*0.5), R=63
            float dy = (qgy - ps[j*2+0]) * 0.5f;
            float dx = (qgx - ps[j*2+1]) * 0.5f;
            float fy = (dy + 1.0f) * 0.5f * 62.0f;
            float fx = (dx + 1.0f) * 0.5f * 62.0f;
            float y0f = floorf(fy), x0f = floorf(fx);
            float wy = fy - y0f, wx = fx - x0f;
            int y0 = min(max((int)y0f, 0), 62);
            int x0 = min(max((int)x0f, 0), 62);
            int y1 = min(y0 + 1, 62), x1 = min(x0 + 1, 62);
            float r00 = rs[y0*63+x0], r01 = rs[y0*63+x1];
            float r10 = rs[y1*63+x0], r11 = rs[y1*63+x1];
            float bia = r00*(1.0f-wx)*(1.0f-wy) + r01*wx*(1.0f-wy)
                      + r10*(1.0f-wx)*wy       + r11*wx*wy;
            float s = dot + bia;
            if (s > runM) {   // rare for this data (near-uniform logits)
                float corr = __expf(runM - s);
                Z *= corr;
#pragma unroll
                for (int c = 0; c < 64; c++) acc[c] *= corr;
                runM = s;
            }
            float p = __expf(s - runM);
            Z += p;
            const float4* vp = (const float4*)Vs[j];
#pragma unroll
            for (int d4 = 0; d4 < 16; d4++) {
                float4 v4 = vp[d4];
                acc[d4*4+0] += p*v4.x; acc[d4*4+1] += p*v4.y;
                acc[d4*4+2] += p*v4.z; acc[d4*4+3] += p*v4.w;
            }
        }
    }
    float inv = 1.0f / Z;
    float* ob = out + ((long)b*Cc + h*DK)*Ll + m;
#pragma unroll
    for (int d = 0; d < 64; d++) ob[(long)d*Ll] = acc[d] * inv;
}

// ---------------------------------------------------------------------------
extern "C" void kernel_launch(void* const* d_in, const int* in_sizes, int n_in,
                              void* d_out, int out_size)
{
    const float* x      = (const float*)d_in[0];
    const float* q_w    = (const float*)d_in[1];
    const float* q_b    = (const float*)d_in[2];
    const float* kv_w   = (const float*)d_in[3];
    const float* kv_b   = (const float*)d_in[4];
    const float* off1_w = (const float*)d_in[5];
    const float* off1_b = (const float*)d_in[6];
    const float* gn_w   = (const float*)d_in[7];
    const float* gn_b   = (const float*)d_in[8];
    const float* off2_w = (const float*)d_in[9];
    const float* rpe    = (const float*)d_in[10];
    const float* proj_w = (const float*)d_in[11];
    const float* proj_b = (const float*)d_in[12];
    float* out = (float*)d_out;

    float *gq, *gim, *gt, *gpos, *gsm, *gkv, *gao;
    cudaGetSymbolAddress((void**)&gq,   g_q);
    cudaGetSymbolAddress((void**)&gim,  g_im);
    cudaGetSymbolAddress((void**)&gt,   g_t);
    cudaGetSymbolAddress((void**)&gpos, g_pos);
    cudaGetSymbolAddress((void**)&gsm,  g_sm);
    cudaGetSymbolAddress((void**)&gkv,  g_kv);
    cudaGetSymbolAddress((void**)&gao,  g_ao);

    // 1. q = conv1x1(x)
    sgemm_bias<<<dim3(64,8,2),256>>>(q_w, x, q_b, gq, 512, 4096, 512,
                                     (long)512*4096, (long)512*4096);
    // 2. im2col for 2x2 stride-2 conv
    im2col_kernel<<<16384,256>>>(gq, gim);
    // 3. t = conv2x2s2(q)
    sgemm_bias<<<dim3(16,8,2),256>>>(off1_w, gim, off1_b, gt, 512, 1024, 2048,
                                     (long)2048*1024, (long)512*1024);
    // 4. GroupNorm + GELU (in place)
    gn_gelu_kernel<<<64,256>>>(gt, gn_w, gn_b);
    // 5. offset conv + reference grid + clip -> pos
    offset_pos_kernel<<<256,256>>>(gt, off2_w, gpos);
    // 6. bilinear sample of x at pos
    sample_kernel<<<2048,128>>>(x, gpos, gsm);
    // 7. kv = conv1x1(sampled)
    sgemm_bias<<<dim3(16,16,2),256>>>(kv_w, gsm, kv_b, gkv, 1024, 1024, 512,
                                      (long)512*1024, (long)1024*1024);
    // 8. fused attention (QK^T + RPE bias + softmax + PV)
    attn_kernel<<<dim3(32,16),128>>>(gq, gkv, gpos, rpe, gao);
    // 9. proj conv -> d_out
    sgemm_bias<<<dim3(64,8,2),256>>>(proj_w, gao, proj_b, out, 512, 4096, 512,
                                     (long)512*4096, (long)512*4096);
}

// round 11
// speedup vs baseline: 1.1046x; 1.1046x over previous
#include <cuda_runtime.h>
#include <math.h>

// Problem constants
#define Bn 2
#define Cc 512
#define Hh 64
#define Ww 64
#define Ll 4096            // H*W
#define N2 1024            // (H/2)*(W/2)
#define NHEADS 8
#define DK 64
#define Rr 63
#define ATT_SCALE (1.0f/4096.0f)   // 1/DK^2

typedef unsigned long long u64;

// ---- packed f32x2 helpers (Blackwell sm_103a packed fp32 pipe) -------------
__device__ __forceinline__ u64 pack2(float lo, float hi) {
    u64 r; asm("mov.b64 %0,{%1,%2};" : "=l"(r) : "f"(lo), "f"(hi)); return r;
}
__device__ __forceinline__ float2 unpack2(u64 v) {
    float2 f; asm("mov.b64 {%0,%1},%2;" : "=f"(f.x), "=f"(f.y) : "l"(v)); return f;
}
__device__ __forceinline__ void ffma2(u64& d, u64 a, u64 b) {
    asm("fma.rn.f32x2 %0,%1,%2,%0;" : "+l"(d) : "l"(a), "l"(b));
}
__device__ __forceinline__ void fmul2(u64& d, u64 a) {
    asm("mul.rn.f32x2 %0,%0,%1;" : "+l"(d) : "l"(a));
}

// Scratch (static device globals — no allocation in kernel_launch).
// __align__(16): these are accessed through float4* in the GEMM kernels.
__device__ __align__(16) float g_q[Bn*Cc*Ll];        // q conv output        [B][C][L]
__device__ __align__(16) float g_im[Bn*2048*N2];     // im2col for 2x2 conv  [B][2048][n]
__device__ __align__(16) float g_t[Bn*Cc*N2];        // offset trunk         [B][C][n]
__device__ __align__(16) float g_pos[Bn*N2*2];       // sampling positions   [B][n][(y,x)]
__device__ __align__(16) float g_sm[Bn*Cc*N2];       // sampled x            [B][C][n]
__device__ __align__(16) float g_kv[Bn*2*Cc*N2];     // k|v                  [B][2C][n]
__device__ __align__(16) float g_ao[Bn*Cc*Ll];       // attention output     [B][C][L]

// ---------------------------------------------------------------------------
// Generic SGEMM: Y[M,N] = W[M,K] @ X[K,N] + bias.  64x64 tile, 4x4 microtile,
// 256 threads, k-step 16, inner loop on the packed f32x2 FMA pipe.
// accp[j][h] holds output rows (4*ty+2h, 4*ty+2h+1), column 4*tx+j.
// ---------------------------------------------------------------------------
__global__ void sgemm_bias(const float* __restrict__ W, const float* __restrict__ X,
                           const float* __restrict__ bias, float* __restrict__ Y,
                           int M, int N, int K, long sX, long sY)
{
    const float* Xb = X + (long)blockIdx.z * sX;
    float* Yb = Y + (long)blockIdx.z * sY;
    int m0 = blockIdx.y * 64, n0 = blockIdx.x * 64;
    __shared__ __align__(16) float As[16][68];   // A transposed: As[k][m]; 272B rows (16B mult)
    __shared__ __align__(16) float Bs[16][64];   // 256B rows
    int tid = threadIdx.x;
    int ai = tid >> 2, aj = (tid & 3) << 2;    // A load: row m0+ai, k offset aj
    int br = tid >> 4, bc = (tid & 15) << 2;   // B load: k row br, col bc
    int ty = tid >> 4, tx = tid & 15;
    u64 accp[4][2] = {};   // zero bits == (0.0f, 0.0f)
    for (int k0 = 0; k0 < K; k0 += 16) {
        float4 av = *(const float4*)(W  + (long)(m0+ai)*K + k0 + aj);
        float4 bv = *(const float4*)(Xb + (long)(k0+br)*N + n0 + bc);
        __syncthreads();   // previous compute done before overwriting smem
        As[aj+0][ai]=av.x; As[aj+1][ai]=av.y; As[aj+2][ai]=av.z; As[aj+3][ai]=av.w;
        *(float4*)&Bs[br][bc] = bv;
        __syncthreads();
#pragma unroll
        for (int kk = 0; kk < 16; kk++) {
            const u64* ap = (const u64*)&As[kk][ty<<2];   // 16B-aligned (272B rows)
            u64 am01 = ap[0], am23 = ap[1];               // packed m-pairs, free
            float4 bq = *(float4*)&Bs[kk][tx<<2];
            u64 b0 = pack2(bq.x, bq.x);   // broadcasts issue on ALU pipe,
            u64 b1 = pack2(bq.y, bq.y);   // dual-issuing against FFMA2
            u64 b2 = pack2(bq.z, bq.z);
            u64 b3 = pack2(bq.w, bq.w);
            ffma2(accp[0][0], am01, b0); ffma2(accp[0][1], am23, b0);
            ffma2(accp[1][0], am01, b1); ffma2(accp[1][1], am23, b1);
            ffma2(accp[2][0], am01, b2); ffma2(accp[2][1], am23, b2);
            ffma2(accp[3][0], am01, b3); ffma2(accp[3][1], am23, b3);
        }
    }
#pragma unroll
    for (int i = 0; i < 4; i++) {
        float bb = bias ? bias[m0+(ty<<2)+i] : 0.0f;
        float* yr = Yb + (long)(m0+(ty<<2)+i)*N + n0 + (tx<<2);
#pragma unroll
        for (int j = 0; j < 4; j++) {
            float2 v = unpack2(accp[j][i>>1]);
            yr[j] = ((i & 1) ? v.y : v.x) + bb;
        }
    }
}

// ---------------------------------------------------------------------------
// im2col for the 2x2 stride-2 conv: im[b][ci*4+ky*2+kx][py*32+px] =
//   q[b][ci][(2py+ky)*64 + 2px+kx]   (matches off1_w [C,C,2,2] layout)
// ---------------------------------------------------------------------------
__global__ void im2col_kernel(const float* __restrict__ q, float* __restrict__ im)
{
    int idx = blockIdx.x * 256 + threadIdx.x;   // exactly B*2048*1024 threads
    int p = idx & 1023;
    int k = (idx >> 10) & 2047;
    int b = idx >> 21;
    int ci = k >> 2, ky = (k >> 1) & 1, kx = k & 1;
    int py = p >> 5, px = p & 31;
    im[idx] = q[((long)b*Cc + ci)*Ll + (2*py+ky)*Ww + 2*px + kx];
}

// ---------------------------------------------------------------------------
// GroupNorm (32 groups of 16 ch x 1024) + exact GELU, in place on g_t.
// One block per (b, group).
// ---------------------------------------------------------------------------
__global__ void gn_gelu_kernel(float* __restrict__ t, const float* __restrict__ w,
                               const float* __restrict__ b)
{
    int bb = blockIdx.x >> 5, g = blockIdx.x & 31;
    float* base = t + ((long)bb*Cc + g*16)*N2;
    int tid = threadIdx.x;
    float s = 0.0f, s2 = 0.0f;
    for (int i = tid; i < 16*N2; i += 256) { float v = base[i]; s += v; s2 += v*v; }
    __shared__ float r1[256], r2[256];
    r1[tid] = s; r2[tid] = s2;
    __syncthreads();
    for (int o = 128; o > 0; o >>= 1) {
        if (tid < o) { r1[tid] += r1[tid+o]; r2[tid] += r2[tid+o]; }
        __syncthreads();
    }
    float mu  = r1[0] * (1.0f/16384.0f);
    float var = r2[0] * (1.0f/16384.0f) - mu*mu;
    float rstd = rsqrtf(var + 1e-5f);
    for (int i = tid; i < 16*N2; i += 256) {
        int c = g*16 + (i >> 10);
        float v = (base[i] - mu) * rstd * w[c] + b[c];
        base[i] = 0.5f * v * (1.0f + erff(v * 0.70710678118654752f));
    }
}

// ---------------------------------------------------------------------------
// offset conv (off2_w [2,512], no bias) + reference grid + clip -> g_pos[b][n][(y,x)]
// One warp per position.
// ---------------------------------------------------------------------------
__global__ void offset_pos_kernel(const float* __restrict__ t, const float* __restrict__ w2,
                                  float* __restrict__ pos)
{
    int gid = blockIdx.x * 8 + (threadIdx.x >> 5);   // b*1024 + n
    int lane = threadIdx.x & 31;
    int b = gid >> 10, n = gid & 1023;
    const float* tb = t + (long)b*Cc*N2 + n;
    float sy = 0.0f, sx = 0.0f;
    for (int c = lane; c < Cc; c += 32) {
        float tv = tb[(long)c*N2];
        sy += w2[c]      * tv;   // channel 0 -> y offset
        sx += w2[Cc + c] * tv;   // channel 1 -> x offset
    }
#pragma unroll
    for (int o = 16; o > 0; o >>= 1) {
        sy += __shfl_down_sync(0xffffffffu, sy, o);
        sx += __shfl_down_sync(0xffffffffu, sx, o);
    }
    if (lane == 0) {
        int iy = n >> 5, ix = n & 31;
        float ry = (0.5f + (float)iy) / 31.0f * 2.0f - 1.0f;
        float rx = (0.5f + (float)ix) / 31.0f * 2.0f - 1.0f;
        pos[gid*2+0] = fminf(fmaxf(sy + ry, -1.0f), 1.0f);
        pos[gid*2+1] = fminf(fmaxf(sx + rx, -1.0f), 1.0f);
    }
}

// ---------------------------------------------------------------------------
// Bilinear grid_sample of x at pos -> g_sm[b][c][n].  One block per (b,n).
// ---------------------------------------------------------------------------
__global__ void sample_kernel(const float* __restrict__ x, const float* __restrict__ pos,
                              float* __restrict__ sm)
{
    int gid = blockIdx.x;
    int b = gid >> 10, n = gid & 1023;
    float py = pos[gid*2+0], px = pos[gid*2+1];
    float fx = (px + 1.0f) * 0.5f * 63.0f;
    float fy = (py + 1.0f) * 0.5f * 63.0f;
    float x0f = floorf(fx), y0f = floorf(fy);
    float wx = fx - x0f, wy = fy - y0f;
    int x0 = min(max((int)x0f, 0), 63), y0 = min(max((int)y0f, 0), 63);
    int x1 = min(x0+1, 63), y1 = min(y0+1, 63);
    float w00 = (1.0f-wx)*(1.0f-wy), w01 = wx*(1.0f-wy);
    float w10 = (1.0f-wx)*wy,        w11 = wx*wy;
    const float* xb = x + (long)b*Cc*Ll;
    for (int c = threadIdx.x; c < Cc; c += 128) {
        const float* xc = xb + (long)c*Ll;
        float v = xc[y0*64+x0]*w00 + xc[y0*64+x1]*w01
                + xc[y1*64+x0]*w10 + xc[y1*64+x1]*w11;
        sm[((long)b*Cc + c)*N2 + n] = v;
    }
}

// ---------------------------------------------------------------------------
// Fused attention: QK^T*scale + bilinear RPE bias + online softmax + PV.
// One thread per query (128 queries/block), K/V staged n-major in smem,
// head RPE table (63x63) in smem.  Dot and PV run on the packed f32x2 pipe.
// ---------------------------------------------------------------------------
__global__ __launch_bounds__(128, 1)
void attn_kernel(const float* __restrict__ q, const float* __restrict__ kv,
                 const float* __restrict__ pos, const float* __restrict__ rpe,
                 float* __restrict__ out)
{
    int bh = blockIdx.y; int b = bh >> 3, h = bh & 7;
    int m = blockIdx.x * 128 + threadIdx.x;
    __shared__ __align__(16) float Ks[32][68];   // [n-in-tile][dk]; 272B rows (16B mult)
    __shared__ __align__(16) float Vs[32][68];
    __shared__ float rs[Rr*Rr];
    __shared__ float ps[64];       // pos (y,x) for the n-tile
    const float* rh = rpe + h*Rr*Rr;
    for (int i = threadIdx.x; i < Rr*Rr; i += 128) rs[i] = rh[i];

    const float* qb = q + ((long)b*Cc + h*DK)*Ll + m;
    u64 q2[32];                    // packed, pre-scaled by 1/DK^2
#pragma unroll
    for (int d2 = 0; d2 < 32; d2++)
        q2[d2] = pack2(qb[(2*d2+0)*Ll] * ATT_SCALE, qb[(2*d2+1)*Ll] * ATT_SCALE);
    float qgy = (float)(m >> 6) / 63.0f * 2.0f - 1.0f;
    float qgx = (float)(m & 63) / 63.0f * 2.0f - 1.0f;

    u64 ac2[32] = {};              // packed PV accumulator (zero bits == 0.0f pair)
    float runM = -1e30f, Z = 0.0f;

    const float* kbase = kv + ((long)b*2*Cc + h*DK)*N2;
    const float* vbase = kbase + (long)Cc*N2;
    const float* pb = pos + b*N2*2;

    for (int n0 = 0; n0 < N2; n0 += 32) {
        __syncthreads();
        for (int e = threadIdx.x; e < 2048; e += 128) {
            int d = e >> 5, j = e & 31;
            Ks[j][d] = kbase[d*N2 + n0 + j];
            Vs[j][d] = vbase[d*N2 + n0 + j];
        }
        if (threadIdx.x < 64) ps[threadIdx.x] = pb[n0*2 + threadIdx.x];
        __syncthreads();

        for (int j = 0; j < 32; j++) {
            const ulonglong2* kp = (const ulonglong2*)Ks[j];   // LDS.128 pairs
            u64 dp[4] = {};
#pragma unroll
            for (int t = 0; t < 16; t++) {
                ulonglong2 kk2 = kp[t];
                ffma2(dp[(2*t)   & 3], q2[2*t],   kk2.x);
                ffma2(dp[(2*t+1) & 3], q2[2*t+1], kk2.y);
            }
            float2 s0 = unpack2(dp[0]), s1 = unpack2(dp[1]);
            float2 s2 = unpack2(dp[2]), s3 = unpack2(dp[3]);
            float dot = ((s0.x+s0.y) + (s1.x+s1.y)) + ((s2.x+s2.y) + (s3.x+s3.y));
            // RPE bias: bilinear sample of rs at disp=((qg - pos)*0.5), R=63
            float dy = (qgy - ps[j*2+0]) * 0.5f;
            float dx = (qgx - ps[j*2+1]) * 0.5f;
            float fy = (dy + 1.0f) * 0.5f * 62.0f;
            float fx = (dx + 1.0f) * 0.5f * 62.0f;
            float y0f = floorf(fy), x0f = floorf(fx);
            float wy = fy - y0f, wx = fx - x0f;
            int y0 = min(max((int)y0f, 0), 62);
            int x0 = min(max((int)x0f, 0), 62);
            int y1 = min(y0 + 1, 62), x1 = min(x0 + 1, 62);
            float r00 = rs[y0*63+x0], r01 = rs[y0*63+x1];
            float r10 = rs[y1*63+x0], r11 = rs[y1*63+x1];
            float bia = r00*(1.0f-wx)*(1.0f-wy) + r01*wx*(1.0f-wy)
                      + r10*(1.0f-wx)*wy       + r11*wx*wy;
            float s = dot + bia;
            if (s > runM) {   // rare for this data (near-uniform logits)
                float corr = __expf(runM - s);
                Z *= corr;
                u64 c2 = pack2(corr, corr);
#pragma unroll
                for (int c = 0; c < 32; c++) fmul2(ac2[c], c2);
                runM = s;
            }
            float p = __expf(s - runM);
            Z += p;
            u64 p2 = pack2(p, p);
            const ulonglong2* vp = (const ulonglong2*)Vs[j];
#pragma unroll
            for (int t = 0; t < 16; t++) {
                ulonglong2 vv = vp[t];
                ffma2(ac2[2*t],   p2, vv.x);
                ffma2(ac2[2*t+1], p2, vv.y);
            }
        }
    }
    float inv = 1.0f / Z;
    float* ob = out + ((long)b*Cc + h*DK)*Ll + m;
#pragma unroll
    for (int d2 = 0; d2 < 32; d2++) {
        float2 v = unpack2(ac2[d2]);
        ob[(long)(2*d2+0)*Ll] = v.x * inv;
        ob[(long)(2*d2+1)*Ll] = v.y * inv;
    }
}

// ---------------------------------------------------------------------------
extern "C" void kernel_launch(void* const* d_in, const int* in_sizes, int n_in,
                              void* d_out, int out_size)
{
    const float* x      = (const float*)d_in[0];
    const float* q_w    = (const float*)d_in[1];
    const float* q_b    = (const float*)d_in[2];
    const float* kv_w   = (const float*)d_in[3];
    const float* kv_b   = (const float*)d_in[4];
    const float* off1_w = (const float*)d_in[5];
    const float* off1_b = (const float*)d_in[6];
    const float* gn_w   = (const float*)d_in[7];
    const float* gn_b   = (const float*)d_in[8];
    const float* off2_w = (const float*)d_in[9];
    const float* rpe    = (const float*)d_in[10];
    const float* proj_w = (const float*)d_in[11];
    const float* proj_b = (const float*)d_in[12];
    float* out = (float*)d_out;

    float *gq, *gim, *gt, *gpos, *gsm, *gkv, *gao;
    cudaGetSymbolAddress((void**)&gq,   g_q);
    cudaGetSymbolAddress((void**)&gim,  g_im);
    cudaGetSymbolAddress((void**)&gt,   g_t);
    cudaGetSymbolAddress((void**)&gpos, g_pos);
    cudaGetSymbolAddress((void**)&gsm,  g_sm);
    cudaGetSymbolAddress((void**)&gkv,  g_kv);
    cudaGetSymbolAddress((void**)&gao,  g_ao);

    // 1. q = conv1x1(x)
    sgemm_bias<<<dim3(64,8,2),256>>>(q_w, x, q_b, gq, 512, 4096, 512,
                                     (long)512*4096, (long)512*4096);
    // 2. im2col for 2x2 stride-2 conv
    im2col_kernel<<<16384,256>>>(gq, gim);
    // 3. t = conv2x2s2(q)
    sgemm_bias<<<dim3(16,8,2),256>>>(off1_w, gim, off1_b, gt, 512, 1024, 2048,
                                     (long)2048*1024, (long)512*1024);
    // 4. GroupNorm + GELU (in place)
    gn_gelu_kernel<<<64,256>>>(gt, gn_w, gn_b);
    // 5. offset conv + reference grid + clip -> pos
    offset_pos_kernel<<<256,256>>>(gt, off2_w, gpos);
    // 6. bilinear sample of x at pos
    sample_kernel<<<2048,128>>>(x, gpos, gsm);
    // 7. kv = conv1x1(sampled)
    sgemm_bias<<<dim3(16,16,2),256>>>(kv_w, gsm, kv_b, gkv, 1024, 1024, 512,
                                      (long)512*1024, (long)1024*1024);
    // 8. fused attention (QK^T + RPE bias + softmax + PV)
    attn_kernel<<<dim3(32,16),128>>>(gq, gkv, gpos, rpe, gao);
    // 9. proj conv -> d_out
    sgemm_bias<<<dim3(64,8,2),256>>>(proj_w, gao, proj_b, out, 512, 4096, 512,
                                     (long)512*4096, (long)512*4096);
}